// round 11
// baseline (speedup 1.0000x reference)
#include <cuda_runtime.h>
#include <math.h>

#define BCn 256

static __device__ float2 g_Xf[BCn*32*32*32];   // [bc][p][k][i]
static __device__ float2 g_Wt[2*32*32*32];     // [li][k][o][i]
static __device__ float  g_enc[BCn*4096];
static __device__ float  g_xn [BCn*4096];
static __device__ float  g_Cm [BCn*1024];
static __device__ float  g_mu[BCn], g_sd[BCn];

struct SMS {
  float2 trigP[128*33];     // [d][k] {cos, -sin}
  float enc[4096], xn[4096], del[4096];
  float h[128*36];          // [d][s], stride 36
  float xw[72*129];
  float dw[128*9];
  float db[128], gg[128], bb[128];
  float dbc[32*80];
};
struct SMX {
  float2 trigP[128*33];
  float2 Wk[32*34];         // [o][i], pad 34
  float2 G[32*33];
  float  Cm[1024];
  float  dp[128];
};

__global__ void __launch_bounds__(512) kA(const float* __restrict__ x) {
  __shared__ float xs[512];
  __shared__ float red[34], red2[16];
  int t = threadIdx.x, bc = blockIdx.x, b = bc >> 5, c = bc & 31;
  float xv = x[(b * 512 + t) * 32 + c];
  float s1 = xv, s2 = xv * xv;
  for (int o = 16; o; o >>= 1) {
    s1 += __shfl_xor_sync(0xFFFFFFFFu, s1, o);
    s2 += __shfl_xor_sync(0xFFFFFFFFu, s2, o);
  }
  if ((t & 31) == 0) { red[t >> 5] = s1; red2[t >> 5] = s2; }
  __syncthreads();
  if (t == 0) {
    float a = 0.f, q = 0.f;
    for (int i = 0; i < 16; i++) { a += red[i]; q += red2[i]; }
    float mu = a * (1.f / 512.f);
    float sd = sqrtf(q * (1.f / 512.f) - mu * mu + 1e-5f);
    red[32] = mu; red[33] = sd;
    g_mu[bc] = mu; g_sd[bc] = sd;
  }
  __syncthreads();
  xs[t] = (xv - red[32]) / red[33];
  __syncthreads();
  for (int e = t; e < 4096; e += 512) {
    int p = e >> 7, d = e & 127, m = d >> 4, pl = d & 15;
    int t0 = p * 16 + pl;
    g_enc[bc * 4096 + e] = (t0 >= 7) ? xs[t0 - 7 + m] : 0.f;
  }
}

__global__ void krepack(const float* __restrict__ Kr, const float* __restrict__ Ki) {
  int idx = blockIdx.x * 256 + threadIdx.x;
  int k = idx & 31, o = (idx >> 5) & 31, i = (idx >> 10) & 31, li = idx >> 15;
  g_Wt[((li * 32 + k) * 32 + o) * 32 + i] = make_float2(Kr[idx], Ki[idx]);
}

__global__ void __launch_bounds__(256, 1) kscan(
    int li, const float* __restrict__ xw_g, const float* __restrict__ dw_g,
    const float* __restrict__ db_g, const float* __restrict__ Al_g,
    const float* __restrict__ lng, const float* __restrict__ lnb) {
  extern __shared__ __align__(16) unsigned char raw[];
  SMS* sm = reinterpret_cast<SMS*>(raw);
  int t = threadIdx.x, lane = t & 31, w = t >> 5, bc = blockIdx.x;

  for (int e = t; e < 4096; e += 256) {
    int d = e >> 5, k = e & 31;
    float sv, cv;
    sincospif((float)(d * k) * (1.0f / 64.0f), &sv, &cv);
    sm->trigP[d * 33 + k] = make_float2(cv, -sv);
  }
  for (int e = t; e < 9216; e += 256) {
    int r = e >> 7, d = e & 127;
    sm->xw[r * 129 + d] = xw_g[li * 9216 + e];
  }
  for (int e = t; e < 1024; e += 256) {
    int d = e >> 3, r = e & 7;
    sm->dw[d * 9 + r] = dw_g[li * 1024 + e];
  }
  if (t < 128) {
    sm->db[t] = db_g[li * 128 + t];
    sm->gg[t] = lng[li * 128 + t];
    sm->bb[t] = lnb[li * 128 + t];
  }
  for (int e = t; e < 4096; e += 256) sm->enc[e] = g_enc[bc * 4096 + e];
  __syncthreads();

  for (int p = w * 4; p < w * 4 + 4; p++) {
    float v[4], s = 0.f, q = 0.f;
    for (int j = 0; j < 4; j++) {
      v[j] = sm->enc[p * 128 + lane + 32 * j];
      s += v[j]; q += v[j] * v[j];
    }
    for (int o = 16; o; o >>= 1) {
      s += __shfl_xor_sync(0xFFFFFFFFu, s, o);
      q += __shfl_xor_sync(0xFFFFFFFFu, q, o);
    }
    float mu = s * (1.f / 128.f);
    float rs = rsqrtf(q * (1.f / 128.f) - mu * mu + 1e-5f);
    for (int j = 0; j < 4; j++) {
      int d = lane + 32 * j;
      sm->xn[p * 128 + d] = (v[j] - mu) * rs * sm->gg[d] + sm->bb[d];
    }
  }
  __syncthreads();

  {
    int p = t >> 3, rr = t & 7;
    float acc[9];
    for (int m = 0; m < 9; m++) acc[m] = 0.f;
    for (int d = 0; d < 128; d++) {
      float xv = sm->xn[p * 128 + d];
      for (int m = 0; m < 9; m++) acc[m] += xv * sm->xw[(rr + 8 * m) * 129 + d];
    }
    for (int m = 0; m < 9; m++) sm->dbc[p * 80 + rr + 8 * m] = acc[m];
  }
  __syncthreads();

  {
    int p = t >> 3, d0 = (t & 7) * 16;
    for (int d = d0; d < d0 + 16; d++) {
      float a = sm->db[d];
      for (int r = 0; r < 8; r++) a += sm->dbc[p * 80 + r] * sm->dw[d * 9 + r];
      sm->del[p * 128 + d] = (a > 20.f) ? a : log1pf(__expf(a));
    }
    for (int q = 0; q < 4; q++) {
      int s = (t & 7) * 4 + q;
      g_Cm[bc * 1024 + p * 32 + s] = sm->dbc[p * 80 + 40 + s];
    }
  }
  __syncthreads();

  int dd = t & 127, s0 = (t >> 7) * 16;
  float A[16], hreg[16];
  for (int q = 0; q < 16; q++) {
    A[q] = -__expf(Al_g[li * 4096 + dd * 32 + s0 + q]);
    hreg[q] = 0.f;
  }
  int kk = t & 31, ig = (t >> 5) * 4;
  float sgn = (kk & 1) ? -1.f : 1.f;
  for (int p = 0; p < 32; p++) {
    float dl = sm->del[p * 128 + dd];
    float bx = dl * sm->xn[p * 128 + dd];
    for (int q = 0; q < 16; q++) {
      hreg[q] = __expf(dl * A[q]) * hreg[q] + bx * sm->dbc[p * 80 + 8 + s0 + q];
      sm->h[dd * 36 + s0 + q] = hreg[q];
    }
    __syncthreads();
    // fold d <-> 128-d: h[dp] := sum, h[128-dp] := diff  (dp=1..63)
    for (int e = t; e < 2016; e += 256) {
      int dp = (e >> 5) + 1, s = e & 31;
      float a = sm->h[dp * 36 + s], b2 = sm->h[(128 - dp) * 36 + s];
      sm->h[dp * 36 + s] = a + b2;
      sm->h[(128 - dp) * 36 + s] = a - b2;
    }
    __syncthreads();
    float4 h0  = *reinterpret_cast<float4*>(&sm->h[ig]);
    float4 h64 = *reinterpret_cast<float4*>(&sm->h[64 * 36 + ig]);
    float ar0 = h0.x + sgn * h64.x, ar1 = h0.y + sgn * h64.y;
    float ar2 = h0.z + sgn * h64.z, ar3 = h0.w + sgn * h64.w;
    float ai0 = 0.f, ai1 = 0.f, ai2 = 0.f, ai3 = 0.f;
    for (int dp = 1; dp < 64; dp++) {
      float2 tp = sm->trigP[dp * 33 + kk];
      float4 su = *reinterpret_cast<float4*>(&sm->h[dp * 36 + ig]);
      float4 dv = *reinterpret_cast<float4*>(&sm->h[(128 - dp) * 36 + ig]);
      ar0 += su.x * tp.x; ai0 += dv.x * tp.y;
      ar1 += su.y * tp.x; ai1 += dv.y * tp.y;
      ar2 += su.z * tp.x; ai2 += dv.z * tp.y;
      ar3 += su.w * tp.x; ai3 += dv.w * tp.y;
    }
    float2* dst = &g_Xf[((bc * 32 + p) * 32 + kk) * 32 + ig];
    *reinterpret_cast<float4*>(dst)     = make_float4(ar0, ai0, ar1, ai1);
    *reinterpret_cast<float4*>(dst + 2) = make_float4(ar2, ai2, ar3, ai3);
    __syncthreads();
  }
  for (int e = t; e < 4096; e += 256) g_xn[bc * 4096 + e] = sm->xn[e];
}

__global__ void __launch_bounds__(256, 2) kmix(int li, const float* __restrict__ Dp_g) {
  extern __shared__ __align__(16) unsigned char raw[];
  SMX* sm = reinterpret_cast<SMX*>(raw);
  int t = threadIdx.x, bc = blockIdx.x;

  for (int e = t; e < 4096; e += 256) {
    int d = e >> 5, k = e & 31;
    float sv, cv;
    sincospif((float)(d * k) * (1.0f / 64.0f), &sv, &cv);
    sm->trigP[d * 33 + k] = make_float2(cv, -sv);
  }
  for (int e = t; e < 1024; e += 256) sm->Cm[e] = g_Cm[bc * 1024 + e];
  if (t < 128) sm->dp[t] = Dp_g[li * 128 + t];
  __syncthreads();

  int p = t >> 3, i0 = (t & 7) * 4;
  for (int k = 0; k < 32; k++) {
    const float2* src = &g_Wt[(li * 32 + k) * 1024];
    for (int e = t; e < 1024; e += 256) {
      int o = e >> 5, i = e & 31;
      sm->Wk[o * 34 + i] = src[e];
    }
    __syncthreads();
    float2 V0 = {0,0}, V1 = {0,0}, V2 = {0,0}, V3 = {0,0};
    for (int o = 0; o < 32; o++) {
      float cm = sm->Cm[p * 32 + o];
      float4 wa = *reinterpret_cast<float4*>(&sm->Wk[o * 34 + i0]);
      float4 wb = *reinterpret_cast<float4*>(&sm->Wk[o * 34 + i0 + 2]);
      V0.x += wa.x * cm; V0.y += wa.y * cm;
      V1.x += wa.z * cm; V1.y += wa.w * cm;
      V2.x += wb.x * cm; V2.y += wb.y * cm;
      V3.x += wb.z * cm; V3.y += wb.w * cm;
    }
    const float2* xfp = &g_Xf[((bc * 32 + p) * 32 + k) * 32 + i0];
    float4 xa = *reinterpret_cast<const float4*>(xfp);
    float4 xb = *reinterpret_cast<const float4*>(xfp + 2);
    float2 g;
    g.x = xa.x * V0.x - xa.y * V0.y + xa.z * V1.x - xa.w * V1.y
        + xb.x * V2.x - xb.y * V2.y + xb.z * V3.x - xb.w * V3.y;
    g.y = xa.x * V0.y + xa.y * V0.x + xa.z * V1.y + xa.w * V1.x
        + xb.x * V2.y + xb.y * V2.x + xb.z * V3.y + xb.w * V3.x;
    for (int o = 1; o < 8; o <<= 1) {
      g.x += __shfl_xor_sync(0xFFFFFFFFu, g.x, o);
      g.y += __shfl_xor_sync(0xFFFFFFFFu, g.y, o);
    }
    if ((t & 7) == 0) sm->G[p * 33 + k] = g;
    __syncthreads();
  }

  int d0 = (t & 7) * 16;
  for (int d = d0; d < d0 + 16; d++) {
    float acc = sm->G[p * 33 + 0].x;
    for (int k = 1; k < 32; k++) {
      float2 gk = sm->G[p * 33 + k];
      float2 tp = sm->trigP[d * 33 + k];
      acc += 2.f * (gk.x * tp.x + gk.y * tp.y);
    }
    int e = p * 128 + d;
    float spec = acc * (1.f / 128.f);
    g_enc[bc * 4096 + e] = g_enc[bc * 4096 + e] + spec + sm->dp[d] * g_xn[bc * 4096 + e];
  }
}

__global__ void __launch_bounds__(128) khead(const float* __restrict__ ow,
                                             const float* __restrict__ ob,
                                             float* __restrict__ out) {
  __shared__ float E[16 * 129];
  __shared__ float Wt[24 * 129];
  int t = threadIdx.x;
  int bc0 = blockIdx.x * 16, pr0 = blockIdx.y * 24;
  int bcl = t & 15, prg = t >> 4;
  float acc[3] = {0.f, 0.f, 0.f};
  for (int k0 = 0; k0 < 4096; k0 += 128) {
    for (int e = t; e < 16 * 128; e += 128) {
      int r = e >> 7, cc = e & 127;
      E[r * 129 + cc] = g_enc[(bc0 + r) * 4096 + k0 + cc];
    }
    for (int e = t; e < 24 * 128; e += 128) {
      int r = e >> 7, cc = e & 127;
      Wt[r * 129 + cc] = ow[(pr0 + r) * 4096 + k0 + cc];
    }
    __syncthreads();
    for (int kkk = 0; kkk < 128; kkk++) {
      float ev = E[bcl * 129 + kkk];
      acc[0] += ev * Wt[(prg * 3 + 0) * 129 + kkk];
      acc[1] += ev * Wt[(prg * 3 + 1) * 129 + kkk];
      acc[2] += ev * Wt[(prg * 3 + 2) * 129 + kkk];
    }
    __syncthreads();
  }
  int bc = bc0 + bcl, b = bc >> 5, c = bc & 31;
  float sd = g_sd[bc], mu = g_mu[bc];
  for (int j = 0; j < 3; j++) {
    int pr = pr0 + prg * 3 + j;
    out[(b * 192 + pr) * 32 + c] = (acc[j] + ob[pr]) * sd + mu;
  }
}

extern "C" void kernel_launch(void* const* d_in, const int* in_sizes, int n_in,
                              void* d_out, int out_size) {
  const float* x    = (const float*)d_in[0];
  const float* xw   = (const float*)d_in[4];
  const float* dw   = (const float*)d_in[5];
  const float* db   = (const float*)d_in[6];
  const float* Alog = (const float*)d_in[7];
  const float* Dp   = (const float*)d_in[8];
  const float* Kr   = (const float*)d_in[9];
  const float* Ki   = (const float*)d_in[10];
  const float* lng  = (const float*)d_in[11];
  const float* lnb  = (const float*)d_in[12];
  const float* ow   = (const float*)d_in[13];
  const float* ob   = (const float*)d_in[14];
  float* out = (float*)d_out;

  cudaFuncSetAttribute(kscan, cudaFuncAttributeMaxDynamicSharedMemorySize, (int)sizeof(SMS));
  cudaFuncSetAttribute(kmix,  cudaFuncAttributeMaxDynamicSharedMemorySize, (int)sizeof(SMX));

  krepack<<<256, 256>>>(Kr, Ki);
  kA<<<BCn, 512>>>(x);
  for (int li = 0; li < 2; li++) {
    kscan<<<BCn, 256, sizeof(SMS)>>>(li, xw, dw, db, Alog, lng, lnb);
    kmix<<<BCn, 256, sizeof(SMX)>>>(li, Dp);
  }
  khead<<<dim3(16, 8), 128>>>(ow, ob, out);
}

// round 12
// speedup vs baseline: 1.0822x; 1.0822x over previous
#include <cuda_runtime.h>
#include <math.h>

#define BCn 256

static __device__ float2 g_Xf[BCn*32*32*32];   // [bc][p][k][i]
static __device__ float2 g_Wt[2*32*32*32];     // [li][k][i][o]
static __device__ float  g_enc[BCn*4096];
static __device__ float  g_xn [BCn*4096];
static __device__ float  g_Cm [BCn*1024];
static __device__ float  g_mu[BCn], g_sd[BCn];

struct SMS {
  float4 tw2[64*16];        // [dp][warp] = {cosA,-sinA,cosB,-sinB}, kkA=2w,kkB=2w+1
  float  su[64*32];         // [dp][i] h_dp + h_(128-dp)   (dp=0 row: h_0)
  float  dv[64*32];         // [dp][i] h_dp - h_(128-dp)   (dp=0 row: h_64)
  float  h[128*33];         // [d][s]
  float  enc[4096], xn[4096], del[4096];
  float  xw[72*129];
  float  dw[128*9];
  float  db[128], gg[128], bb[128];
  float  dbc[32*80];
};
struct SMX {
  float2 trigH[65*33];      // [dp][k] {cos, -sin}, dp 0..64
  float2 Wk[32*33];         // [i][o]
  float2 G[32*33];
  float  Cm[1024];
  float  dp[128];
};

__global__ void __launch_bounds__(512) kA(const float* __restrict__ x) {
  __shared__ float xs[512];
  __shared__ float red[34], red2[16];
  int t = threadIdx.x, bc = blockIdx.x, b = bc >> 5, c = bc & 31;
  float xv = x[(b * 512 + t) * 32 + c];
  float s1 = xv, s2 = xv * xv;
  for (int o = 16; o; o >>= 1) {
    s1 += __shfl_xor_sync(0xFFFFFFFFu, s1, o);
    s2 += __shfl_xor_sync(0xFFFFFFFFu, s2, o);
  }
  if ((t & 31) == 0) { red[t >> 5] = s1; red2[t >> 5] = s2; }
  __syncthreads();
  if (t == 0) {
    float a = 0.f, q = 0.f;
    for (int i = 0; i < 16; i++) { a += red[i]; q += red2[i]; }
    float mu = a * (1.f / 512.f);
    float sd = sqrtf(q * (1.f / 512.f) - mu * mu + 1e-5f);
    red[32] = mu; red[33] = sd;
    g_mu[bc] = mu; g_sd[bc] = sd;
  }
  __syncthreads();
  xs[t] = (xv - red[32]) / red[33];
  __syncthreads();
  for (int e = t; e < 4096; e += 512) {
    int p = e >> 7, d = e & 127, m = d >> 4, pl = d & 15;
    int t0 = p * 16 + pl;
    g_enc[bc * 4096 + e] = (t0 >= 7) ? xs[t0 - 7 + m] : 0.f;
  }
}

__global__ void krepack(const float* __restrict__ Kr, const float* __restrict__ Ki) {
  int idx = blockIdx.x * 256 + threadIdx.x;
  int k = idx & 31, o = (idx >> 5) & 31, i = (idx >> 10) & 31, li = idx >> 15;
  g_Wt[((li * 32 + k) * 32 + i) * 32 + o] = make_float2(Kr[idx], Ki[idx]);
}

__global__ void __launch_bounds__(512, 1) kscan(
    int li, const float* __restrict__ xw_g, const float* __restrict__ dw_g,
    const float* __restrict__ db_g, const float* __restrict__ Al_g,
    const float* __restrict__ lng, const float* __restrict__ lnb) {
  extern __shared__ __align__(16) unsigned char raw[];
  SMS* sm = reinterpret_cast<SMS*>(raw);
  int t = threadIdx.x, lane = t & 31, w = t >> 5, bc = blockIdx.x;

  // twiddle table: per (dp, warp) the pair kkA=2w, kkB=2w+1
  for (int e = t; e < 1024; e += 512) {
    int dp = e >> 4, ww = e & 15;
    float sA, cA, sB, cB;
    sincospif((float)(dp * 2 * ww) * (1.0f / 64.0f), &sA, &cA);
    sincospif((float)(dp * (2 * ww + 1)) * (1.0f / 64.0f), &sB, &cB);
    sm->tw2[e] = make_float4(cA, -sA, cB, -sB);
  }
  for (int e = t; e < 9216; e += 512) {
    int r = e >> 7, d = e & 127;
    sm->xw[r * 129 + d] = xw_g[li * 9216 + e];
  }
  for (int e = t; e < 1024; e += 512) {
    int d = e >> 3, r = e & 7;
    sm->dw[d * 9 + r] = dw_g[li * 1024 + e];
  }
  if (t < 128) {
    sm->db[t] = db_g[li * 128 + t];
    sm->gg[t] = lng[li * 128 + t];
    sm->bb[t] = lnb[li * 128 + t];
  }
  for (int e = t; e < 4096; e += 512) sm->enc[e] = g_enc[bc * 4096 + e];
  __syncthreads();

  // LayerNorm: warp w -> tokens 2w, 2w+1
  for (int pp = 0; pp < 2; pp++) {
    int p = w * 2 + pp;
    float v[4], s = 0.f, q = 0.f;
    for (int j = 0; j < 4; j++) {
      v[j] = sm->enc[p * 128 + lane + 32 * j];
      s += v[j]; q += v[j] * v[j];
    }
    for (int o = 16; o; o >>= 1) {
      s += __shfl_xor_sync(0xFFFFFFFFu, s, o);
      q += __shfl_xor_sync(0xFFFFFFFFu, q, o);
    }
    float mu = s * (1.f / 128.f);
    float rs = rsqrtf(q * (1.f / 128.f) - mu * mu + 1e-5f);
    for (int j = 0; j < 4; j++) {
      int d = lane + 32 * j;
      sm->xn[p * 128 + d] = (v[j] - mu) * rs * sm->gg[d] + sm->bb[d];
    }
  }
  __syncthreads();

  // projection dbc[p][r], thread -> (p = t>>4, rt = t&15), r = rt + 16m
  {
    int p = t >> 4, rt = t & 15;
    float a0 = 0, a1 = 0, a2 = 0, a3 = 0, a4 = 0;
    const float* xp = &sm->xn[p * 128];
    for (int d = 0; d < 128; d++) {
      float xv = xp[d];
      a0 += xv * sm->xw[rt * 129 + d];
      a1 += xv * sm->xw[(rt + 16) * 129 + d];
      a2 += xv * sm->xw[(rt + 32) * 129 + d];
      a3 += xv * sm->xw[(rt + 48) * 129 + d];
      if (rt < 8) a4 += xv * sm->xw[(rt + 64) * 129 + d];
    }
    sm->dbc[p * 80 + rt] = a0;
    sm->dbc[p * 80 + rt + 16] = a1;
    sm->dbc[p * 80 + rt + 32] = a2;
    sm->dbc[p * 80 + rt + 48] = a3;
    if (rt < 8) sm->dbc[p * 80 + rt + 64] = a4;
  }
  __syncthreads();

  // delta = softplus(dbc[:,:8] @ dw^T + db); Cm -> global
  {
    int p = t >> 4, d0 = (t & 15) * 8;
    for (int d = d0; d < d0 + 8; d++) {
      float a = sm->db[d];
      for (int r = 0; r < 8; r++) a += sm->dbc[p * 80 + r] * sm->dw[d * 9 + r];
      sm->del[p * 128 + d] = (a > 20.f) ? a : log1pf(__expf(a));
    }
    int s2 = (t & 15) * 2;
    g_Cm[bc * 1024 + p * 32 + s2]     = sm->dbc[p * 80 + 40 + s2];
    g_Cm[bc * 1024 + p * 32 + s2 + 1] = sm->dbc[p * 80 + 40 + s2 + 1];
  }
  __syncthreads();

  // scan (thread: d = t>>2, 8 states) + DFT (lane = i, warp = k-pair)
  int dd = t >> 2, s0 = (t & 3) * 8;
  float A[8], hreg[8];
  for (int q = 0; q < 8; q++) {
    A[q] = -__expf(Al_g[li * 4096 + dd * 32 + s0 + q]);
    hreg[q] = 0.f;
  }
  int kkA = 2 * w;

  for (int p = 0; p < 32; p++) {
    float dl = sm->del[p * 128 + dd];
    float bx = dl * sm->xn[p * 128 + dd];
#pragma unroll
    for (int q = 0; q < 8; q++) {
      hreg[q] = __expf(dl * A[q]) * hreg[q] + bx * sm->dbc[p * 80 + 8 + s0 + q];
      sm->h[dd * 33 + s0 + q] = hreg[q];
    }
    __syncthreads();
    // fold into su/dv planes
#pragma unroll
    for (int e0 = 0; e0 < 4; e0++) {
      int e = t + 512 * e0;
      int dp = e >> 5, i = e & 31;
      if (dp == 0) {
        sm->su[i] = sm->h[i];                 // h_0
        sm->dv[i] = sm->h[64 * 33 + i];       // h_64
      } else {
        float a = sm->h[dp * 33 + i], b2 = sm->h[(128 - dp) * 33 + i];
        sm->su[dp * 32 + i] = a + b2;
        sm->dv[dp * 32 + i] = a - b2;
      }
    }
    __syncthreads();
    // X_k = sgn_k*h64 + sum_dp { su*cos + i*dv*(-sin) }  (dp=0 term: su*1)
    float dv0 = sm->dv[lane];
    float arA = dv0, arB = -dv0, aiA = 0.f, aiB = 0.f;
#pragma unroll 8
    for (int dp = 0; dp < 64; dp++) {
      float4 tw = sm->tw2[dp * 16 + w];
      float suv = sm->su[dp * 32 + lane];
      float dvv = sm->dv[dp * 32 + lane];
      arA += suv * tw.x; aiA += dvv * tw.y;
      arB += suv * tw.z; aiB += dvv * tw.w;
    }
    float2* base = &g_Xf[((bc * 32 + p) * 32) * 32];
    base[kkA * 32 + lane]       = make_float2(arA, aiA);
    base[(kkA + 1) * 32 + lane] = make_float2(arB, aiB);
  }
  for (int e = t; e < 4096; e += 512) g_xn[bc * 4096 + e] = sm->xn[e];
}

__global__ void __launch_bounds__(256, 3) kmix(int li, const float* __restrict__ Dp_g) {
  extern __shared__ __align__(16) unsigned char raw[];
  SMX* sm = reinterpret_cast<SMX*>(raw);
  int t = threadIdx.x, bc = blockIdx.x;

  for (int e = t; e < 2080; e += 256) {
    int d = e >> 5, k = e & 31;
    float sv, cv;
    sincospif((float)(d * k) * (1.0f / 64.0f), &sv, &cv);
    sm->trigH[d * 33 + k] = make_float2(cv, -sv);
  }
  for (int e = t; e < 1024; e += 256) sm->Cm[e] = g_Cm[bc * 1024 + e];
  if (t < 128) sm->dp[t] = Dp_g[li * 128 + t];
  __syncthreads();

  int p = t >> 3, i0 = (t & 7) * 4;
  for (int k = 0; k < 32; k++) {
    const float2* src = &g_Wt[(li * 32 + k) * 1024];
    for (int e = t; e < 1024; e += 256) {
      int i = e >> 5, o = e & 31;
      sm->Wk[i * 33 + o] = src[e];
    }
    __syncthreads();
    float2 g = make_float2(0.f, 0.f);
    for (int q = 0; q < 4; q++) {
      int i = i0 + q;
      float2 V = make_float2(0.f, 0.f);
      for (int o = 0; o < 32; o++) {
        float cm = sm->Cm[p * 32 + o];
        float2 wv = sm->Wk[i * 33 + o];
        V.x += wv.x * cm; V.y += wv.y * cm;
      }
      float2 xf = g_Xf[((bc * 32 + p) * 32 + k) * 32 + i];
      g.x += xf.x * V.x - xf.y * V.y;
      g.y += xf.x * V.y + xf.y * V.x;
    }
    for (int o = 1; o < 8; o <<= 1) {
      g.x += __shfl_xor_sync(0xFFFFFFFFu, g.x, o);
      g.y += __shfl_xor_sync(0xFFFFFFFFu, g.y, o);
    }
    if ((t & 7) == 0) sm->G[p * 33 + k] = g;
    __syncthreads();
  }

  // paired iDFT: d and 128-d share cos, negate sin part
  int j = t & 7;
  float g0 = sm->G[p * 33].x;
  for (int m = 0; m < 8; m++) {
    int dp = j * 8 + m;
    float accC = g0, accS = 0.f;
    for (int k = 1; k < 32; k++) {
      float2 gk = sm->G[p * 33 + k];
      float2 tp = sm->trigH[dp * 33 + k];
      accC += 2.f * gk.x * tp.x;
      accS += 2.f * gk.y * tp.y;
    }
    int e = p * 128 + dp;
    float y = (accC + accS) * (1.f / 128.f);
    g_enc[bc * 4096 + e] += y + sm->dp[dp] * g_xn[bc * 4096 + e];
    if (dp >= 1) {
      int d2 = 128 - dp, e2 = p * 128 + d2;
      float y2 = (accC - accS) * (1.f / 128.f);
      g_enc[bc * 4096 + e2] += y2 + sm->dp[d2] * g_xn[bc * 4096 + e2];
    }
  }
  if (j == 0) {  // d = 64: cos(pi k) = (-1)^k, sin = 0
    float acc = g0;
    for (int k = 1; k < 32; k++)
      acc += 2.f * sm->G[p * 33 + k].x * ((k & 1) ? -1.f : 1.f);
    int e = p * 128 + 64;
    g_enc[bc * 4096 + e] += acc * (1.f / 128.f) + sm->dp[64] * g_xn[bc * 4096 + e];
  }
}

__global__ void __launch_bounds__(128) khead(const float* __restrict__ ow,
                                             const float* __restrict__ ob,
                                             float* __restrict__ out) {
  __shared__ float E[16 * 129];
  __shared__ float Wt[24 * 129];
  int t = threadIdx.x;
  int bc0 = blockIdx.x * 16, pr0 = blockIdx.y * 24;
  int bcl = t & 15, prg = t >> 4;
  float acc[3] = {0.f, 0.f, 0.f};
  for (int k0 = 0; k0 < 4096; k0 += 128) {
    for (int e = t; e < 16 * 128; e += 128) {
      int r = e >> 7, cc = e & 127;
      E[r * 129 + cc] = g_enc[(bc0 + r) * 4096 + k0 + cc];
    }
    for (int e = t; e < 24 * 128; e += 128) {
      int r = e >> 7, cc = e & 127;
      Wt[r * 129 + cc] = ow[(pr0 + r) * 4096 + k0 + cc];
    }
    __syncthreads();
    for (int kkk = 0; kkk < 128; kkk++) {
      float ev = E[bcl * 129 + kkk];
      acc[0] += ev * Wt[(prg * 3 + 0) * 129 + kkk];
      acc[1] += ev * Wt[(prg * 3 + 1) * 129 + kkk];
      acc[2] += ev * Wt[(prg * 3 + 2) * 129 + kkk];
    }
    __syncthreads();
  }
  int bc = bc0 + bcl, b = bc >> 5, c = bc & 31;
  float sd = g_sd[bc], mu = g_mu[bc];
  for (int jj = 0; jj < 3; jj++) {
    int pr = pr0 + prg * 3 + jj;
    out[(b * 192 + pr) * 32 + c] = (acc[jj] + ob[pr]) * sd + mu;
  }
}

extern "C" void kernel_launch(void* const* d_in, const int* in_sizes, int n_in,
                              void* d_out, int out_size) {
  const float* x    = (const float*)d_in[0];
  const float* xw   = (const float*)d_in[4];
  const float* dw   = (const float*)d_in[5];
  const float* db   = (const float*)d_in[6];
  const float* Alog = (const float*)d_in[7];
  const float* Dp   = (const float*)d_in[8];
  const float* Kr   = (const float*)d_in[9];
  const float* Ki   = (const float*)d_in[10];
  const float* lng  = (const float*)d_in[11];
  const float* lnb  = (const float*)d_in[12];
  const float* ow   = (const float*)d_in[13];
  const float* ob   = (const float*)d_in[14];
  float* out = (float*)d_out;

  cudaFuncSetAttribute(kscan, cudaFuncAttributeMaxDynamicSharedMemorySize, (int)sizeof(SMS));
  cudaFuncSetAttribute(kmix,  cudaFuncAttributeMaxDynamicSharedMemorySize, (int)sizeof(SMX));

  krepack<<<256, 256>>>(Kr, Ki);
  kA<<<BCn, 512>>>(x);
  for (int li = 0; li < 2; li++) {
    kscan<<<BCn, 512, sizeof(SMS)>>>(li, xw, dw, db, Alog, lng, lnb);
    kmix<<<BCn, 256, sizeof(SMX)>>>(li, Dp);
  }
  khead<<<dim3(16, 8), 128>>>(ow, ob, out);
}